// round 1
// baseline (speedup 1.0000x reference)
#include <cuda_runtime.h>
#include <cuda_bf16.h>
#include <cstdint>
#include <cmath>

#define B_   8
#define LQ   1024
#define LK   8192
#define D_   256
#define DC   128
#define EPSF 1e-6f

// ---------------- scratch (no allocations allowed) ----------------
__device__ __nv_bfloat16 g_qt[B_ * LQ * DC];     // q~ = q @ W_up     (2 MB)
__device__ float         g_qsq[B_ * LQ];
__device__ __nv_bfloat16 g_kc[B_ * LK * DC];     // dequantized codes (16 MB)
__device__ float         g_ksq[B_ * LK];
__device__ __nv_bfloat16 g_G[DC * DC];           // G = W^T W

// ---------------- mma helpers ----------------
__device__ __forceinline__ uint32_t sptr(const void* p) {
    return (uint32_t)__cvta_generic_to_shared(p);
}
__device__ __forceinline__ void ldsm4(uint32_t& a0, uint32_t& a1, uint32_t& a2, uint32_t& a3, uint32_t addr) {
    asm volatile("ldmatrix.sync.aligned.m8n8.x4.shared.b16 {%0,%1,%2,%3}, [%4];"
                 : "=r"(a0), "=r"(a1), "=r"(a2), "=r"(a3) : "r"(addr));
}
__device__ __forceinline__ void ldsm2(uint32_t& b0, uint32_t& b1, uint32_t addr) {
    asm volatile("ldmatrix.sync.aligned.m8n8.x2.shared.b16 {%0,%1}, [%2];"
                 : "=r"(b0), "=r"(b1) : "r"(addr));
}
__device__ __forceinline__ void mma16816(float& c0, float& c1, float& c2, float& c3,
                                         uint32_t a0, uint32_t a1, uint32_t a2, uint32_t a3,
                                         uint32_t b0, uint32_t b1) {
    asm volatile("mma.sync.aligned.m16n8k16.row.col.f32.bf16.bf16.f32 "
                 "{%0,%1,%2,%3}, {%4,%5,%6,%7}, {%8,%9}, {%0,%1,%2,%3};"
                 : "+f"(c0), "+f"(c1), "+f"(c2), "+f"(c3)
                 : "r"(a0), "r"(a1), "r"(a2), "r"(a3), "r"(b0), "r"(b1));
}

// ---------------- kernel 1: G = W^T W (fp32 -> bf16) ----------------
__global__ void k_G(const float* __restrict__ W) {
    int c1 = blockIdx.x, c2 = threadIdx.x;
    float acc = 0.f;
    #pragma unroll 4
    for (int d = 0; d < D_; d++) acc += W[d * DC + c1] * W[d * DC + c2];
    g_G[c1 * DC + c2] = __float2bfloat16(acc);
}

// ---------------- kernel 2: q~ = q @ W  and  q_sq ----------------
__global__ void k_prepq(const float* __restrict__ q, const float* __restrict__ W) {
    const int row = blockIdx.x;                 // b*LQ + l
    __shared__ float qs[D_];
    __shared__ float red[128];
    const int t = threadIdx.x;                  // 128 threads
    float a = q[row * D_ + t];
    float b = q[row * D_ + t + 128];
    qs[t] = a; qs[t + 128] = b;
    red[t] = a * a + b * b;
    __syncthreads();
    float acc = 0.f;
    #pragma unroll 4
    for (int d = 0; d < D_; d++) acc += qs[d] * W[d * DC + t];
    g_qt[row * DC + t] = __float2bfloat16(acc);
    for (int s = 64; s > 0; s >>= 1) {
        if (t < s) red[t] += red[t + s];
        __syncthreads();
    }
    if (t == 0) g_qsq[row] = red[0];
}

// ---------------- kernel 3: dequant codes + k_sq = kc^T G kc ----------------
#define PSTRIDE 136
#define SMEM_PREPK (2 * 128 * PSTRIDE * 2 + 512)

__global__ void k_prepk(const int* __restrict__ kq,
                        const float* __restrict__ kscale,
                        const float* __restrict__ kzero) {
    extern __shared__ char sm[];
    __nv_bfloat16* kcs  = (__nv_bfloat16*)sm;                 // [128][136]
    __nv_bfloat16* Gs   = kcs + 128 * PSTRIDE;                // [128][136]
    float*         ksqs = (float*)(Gs + 128 * PSTRIDE);       // [128]

    const int t    = threadIdx.x;        // 256
    const int row0 = blockIdx.x * 128;   // global row in [0, B*LK)
    const int b    = row0 / LK;

    // dequantize 128x128 codes into smem (bf16) and global scratch
    {
        const int c4 = (t & 31) * 4;
        const float4 sc = *(const float4*)(kscale + b * DC + c4);
        const float4 zr = *(const float4*)(kzero + b * DC + c4);
        const int rb = t >> 5;
        #pragma unroll
        for (int i = 0; i < 16; i++) {
            const int r = rb + i * 8;
            const int4 code = *(const int4*)(kq + (size_t)(row0 + r) * DC + c4);
            __nv_bfloat162 p0, p1;
            p0.x = __float2bfloat16(sc.x * ((float)code.x - zr.x));
            p0.y = __float2bfloat16(sc.y * ((float)code.y - zr.y));
            p1.x = __float2bfloat16(sc.z * ((float)code.z - zr.z));
            p1.y = __float2bfloat16(sc.w * ((float)code.w - zr.w));
            *(__nv_bfloat162*)&kcs[r * PSTRIDE + c4]     = p0;
            *(__nv_bfloat162*)&kcs[r * PSTRIDE + c4 + 2] = p1;
            *(__nv_bfloat162*)&g_kc[(size_t)(row0 + r) * DC + c4]     = p0;
            *(__nv_bfloat162*)&g_kc[(size_t)(row0 + r) * DC + c4 + 2] = p1;
        }
    }
    // load G
    {
        const int r = t >> 1, ch = (t & 1) * 64;
        const uint4* src = (const uint4*)(g_G + r * DC + ch);
        #pragma unroll
        for (int i = 0; i < 8; i++) *(uint4*)&Gs[r * PSTRIDE + ch + i * 8] = src[i];
    }
    if (t < 128) ksqs[t] = 0.f;
    __syncthreads();

    // kg = kc @ G   (G symmetric -> B[n][k] = G[n][k]);  ksq = row-dot(kc, kg)
    const int w = t >> 5, lane = t & 31;
    const int m0 = (w >> 2) * 64, n0 = (w & 3) * 32;
    const int gid = lane >> 2, tid2 = lane & 3;
    const int arow = lane & 15, acol = ((lane >> 4) << 3);
    const int brow = lane & 7,  bcol = (((lane >> 3) & 1) << 3);

    float acc[4][4][4];
    #pragma unroll
    for (int i = 0; i < 4; i++)
        #pragma unroll
        for (int j = 0; j < 4; j++)
            #pragma unroll
            for (int c = 0; c < 4; c++) acc[i][j][c] = 0.f;

    #pragma unroll
    for (int ks = 0; ks < 8; ks++) {
        const int k0 = ks * 16;
        uint32_t A[4][4], Bf[4][2];
        #pragma unroll
        for (int ms = 0; ms < 4; ms++)
            ldsm4(A[ms][0], A[ms][1], A[ms][2], A[ms][3],
                  sptr(&kcs[(m0 + ms * 16 + arow) * PSTRIDE + k0 + acol]));
        #pragma unroll
        for (int ns = 0; ns < 4; ns++)
            ldsm2(Bf[ns][0], Bf[ns][1],
                  sptr(&Gs[(n0 + ns * 8 + brow) * PSTRIDE + k0 + bcol]));
        #pragma unroll
        for (int ms = 0; ms < 4; ms++)
            #pragma unroll
            for (int ns = 0; ns < 4; ns++)
                mma16816(acc[ms][ns][0], acc[ms][ns][1], acc[ms][ns][2], acc[ms][ns][3],
                         A[ms][0], A[ms][1], A[ms][2], A[ms][3], Bf[ns][0], Bf[ns][1]);
    }

    #pragma unroll
    for (int ms = 0; ms < 4; ms++) {
        const int rA = m0 + ms * 16 + gid, rB = rA + 8;
        float sA = 0.f, sB = 0.f;
        #pragma unroll
        for (int ns = 0; ns < 4; ns++) {
            const int c0 = n0 + ns * 8 + tid2 * 2;
            sA += acc[ms][ns][0] * __bfloat162float(kcs[rA * PSTRIDE + c0]);
            sA += acc[ms][ns][1] * __bfloat162float(kcs[rA * PSTRIDE + c0 + 1]);
            sB += acc[ms][ns][2] * __bfloat162float(kcs[rB * PSTRIDE + c0]);
            sB += acc[ms][ns][3] * __bfloat162float(kcs[rB * PSTRIDE + c0 + 1]);
        }
        atomicAdd(&ksqs[rA], sA);
        atomicAdd(&ksqs[rB], sB);
    }
    __syncthreads();
    if (t < 128) g_ksq[row0 + t] = ksqs[t];
}

// ---------------- kernel 4: main — qk MMA + hyperbolic distance ----------------
#define SMEM_MAIN (2 * 128 * PSTRIDE * 2 + 1024)

__device__ __forceinline__ float dist_f(float qs, float ks, float qk) {
    float diff = fmaxf(qs + ks - 2.f * qk, 0.f);
    float qn = fminf(qs, 1.f - EPSF);
    float kn = fminf(ks, 1.f - EPSF);
    float denom = (1.f - qn) * (1.f - kn) + EPSF;
    return acoshf(1.f + 2.f * diff / denom);
}

__global__ void k_main(float* __restrict__ out) {
    extern __shared__ char sm[];
    __nv_bfloat16* qts  = (__nv_bfloat16*)sm;             // [128][136]
    __nv_bfloat16* kcs  = qts + 128 * PSTRIDE;            // [128][136]
    float*         qsqs = (float*)(kcs + 128 * PSTRIDE);  // [128]
    float*         ksqs = qsqs + 128;                     // [128]

    const int t = threadIdx.x;                            // 256
    const int kb = blockIdx.x, qb = blockIdx.y, b = blockIdx.z;
    const int q0 = qb * 128, k0t = kb * 128;

    {
        const int r = t >> 1, ch = (t & 1) * 64;
        const uint4* s1 = (const uint4*)(g_qt + ((size_t)(b * LQ + q0 + r)) * DC + ch);
        const uint4* s2 = (const uint4*)(g_kc + ((size_t)(b * LK + k0t + r)) * DC + ch);
        #pragma unroll
        for (int i = 0; i < 8; i++) *(uint4*)&qts[r * PSTRIDE + ch + i * 8] = s1[i];
        #pragma unroll
        for (int i = 0; i < 8; i++) *(uint4*)&kcs[r * PSTRIDE + ch + i * 8] = s2[i];
    }
    if (t < 128) {
        qsqs[t] = g_qsq[b * LQ + q0 + t];
        ksqs[t] = g_ksq[b * LK + k0t + t];
    }
    __syncthreads();

    const int w = t >> 5, lane = t & 31;
    const int m0 = (w >> 2) * 64, n0 = (w & 3) * 32;
    const int gid = lane >> 2, tid2 = lane & 3;
    const int arow = lane & 15, acol = ((lane >> 4) << 3);
    const int brow = lane & 7,  bcol = (((lane >> 3) & 1) << 3);

    float acc[4][4][4];
    #pragma unroll
    for (int i = 0; i < 4; i++)
        #pragma unroll
        for (int j = 0; j < 4; j++)
            #pragma unroll
            for (int c = 0; c < 4; c++) acc[i][j][c] = 0.f;

    #pragma unroll
    for (int ks = 0; ks < 8; ks++) {
        const int k0 = ks * 16;
        uint32_t A[4][4], Bf[4][2];
        #pragma unroll
        for (int ms = 0; ms < 4; ms++)
            ldsm4(A[ms][0], A[ms][1], A[ms][2], A[ms][3],
                  sptr(&qts[(m0 + ms * 16 + arow) * PSTRIDE + k0 + acol]));
        #pragma unroll
        for (int ns = 0; ns < 4; ns++)
            ldsm2(Bf[ns][0], Bf[ns][1],
                  sptr(&kcs[(n0 + ns * 8 + brow) * PSTRIDE + k0 + bcol]));
        #pragma unroll
        for (int ms = 0; ms < 4; ms++)
            #pragma unroll
            for (int ns = 0; ns < 4; ns++)
                mma16816(acc[ms][ns][0], acc[ms][ns][1], acc[ms][ns][2], acc[ms][ns][3],
                         A[ms][0], A[ms][1], A[ms][2], A[ms][3], Bf[ns][0], Bf[ns][1]);
    }

    #pragma unroll
    for (int ms = 0; ms < 4; ms++) {
        const int rA = m0 + ms * 16 + gid, rB = rA + 8;
        const float qsA = qsqs[rA], qsB = qsqs[rB];
        const size_t baseA = ((size_t)(b * LQ + q0 + rA)) * LK + k0t;
        const size_t baseB = baseA + (size_t)8 * LK;
        #pragma unroll
        for (int ns = 0; ns < 4; ns++) {
            const int c0 = n0 + ns * 8 + tid2 * 2;
            const float ks0 = ksqs[c0], ks1 = ksqs[c0 + 1];
            float2 o0, o1;
            o0.x = dist_f(qsA, ks0, acc[ms][ns][0]);
            o0.y = dist_f(qsA, ks1, acc[ms][ns][1]);
            o1.x = dist_f(qsB, ks0, acc[ms][ns][2]);
            o1.y = dist_f(qsB, ks1, acc[ms][ns][3]);
            *(float2*)(out + baseA + c0) = o0;
            *(float2*)(out + baseB + c0) = o1;
        }
    }
}

// ---------------- launch ----------------
extern "C" void kernel_launch(void* const* d_in, const int* in_sizes, int n_in,
                              void* d_out, int out_size) {
    const float* q   = (const float*)d_in[0];
    const int*   kq  = (const int*)d_in[1];
    const float* ksc = (const float*)d_in[2];
    const float* kz  = (const float*)d_in[3];
    const float* W   = (const float*)d_in[4];
    float* out = (float*)d_out;
    (void)in_sizes; (void)n_in; (void)out_size;

    cudaFuncSetAttribute(k_prepk, cudaFuncAttributeMaxDynamicSharedMemorySize, SMEM_PREPK);
    cudaFuncSetAttribute(k_main,  cudaFuncAttributeMaxDynamicSharedMemorySize, SMEM_MAIN);

    k_G<<<DC, DC>>>(W);
    k_prepq<<<B_ * LQ, 128>>>(q, W);
    k_prepk<<<(B_ * LK) / 128, 256, SMEM_PREPK>>>(kq, ksc, kz);
    k_main<<<dim3(LK / 128, LQ / 128, B_), 256, SMEM_MAIN>>>(out);
}

// round 2
// speedup vs baseline: 1.2560x; 1.2560x over previous
#include <cuda_runtime.h>
#include <cuda_bf16.h>
#include <cstdint>
#include <cmath>

#define B_   8
#define LQ   1024
#define LK   8192
#define D_   256
#define DC   128
#define EPSF 1e-6f

// ---------------- scratch (no allocations allowed) ----------------
__device__ __nv_bfloat16  g_qt[B_ * LQ * DC];     // q~ = q @ W_up     (2 MB)
__device__ float          g_qsq[B_ * LQ];
__device__ __nv_bfloat16  g_kc[B_ * LK * DC];     // dequantized codes (16 MB)
__device__ float          g_ksq[B_ * LK];
__device__ __nv_bfloat16  g_G[DC * DC];           // G = W^T W (bf16)
__device__ __nv_bfloat162 g_Wb2[(D_ / 2) * DC];   // W paired along d: (W[2d,c],W[2d+1,c])

// ---------------- fast math ----------------
__device__ __forceinline__ float fast_rcp(float x)  { float r; asm("rcp.approx.f32 %0, %1;"  : "=f"(r) : "f"(x)); return r; }
__device__ __forceinline__ float fast_sqrt(float x) { float r; asm("sqrt.approx.f32 %0, %1;" : "=f"(r) : "f"(x)); return r; }
__device__ __forceinline__ float fast_lg2(float x)  { float r; asm("lg2.approx.f32 %0, %1;"  : "=f"(r) : "f"(x)); return r; }

// ---------------- mma helpers ----------------
__device__ __forceinline__ uint32_t sptr(const void* p) {
    return (uint32_t)__cvta_generic_to_shared(p);
}
__device__ __forceinline__ void ldsm4(uint32_t& a0, uint32_t& a1, uint32_t& a2, uint32_t& a3, uint32_t addr) {
    asm volatile("ldmatrix.sync.aligned.m8n8.x4.shared.b16 {%0,%1,%2,%3}, [%4];"
                 : "=r"(a0), "=r"(a1), "=r"(a2), "=r"(a3) : "r"(addr));
}
__device__ __forceinline__ void ldsm2(uint32_t& b0, uint32_t& b1, uint32_t addr) {
    asm volatile("ldmatrix.sync.aligned.m8n8.x2.shared.b16 {%0,%1}, [%2];"
                 : "=r"(b0), "=r"(b1) : "r"(addr));
}
__device__ __forceinline__ void mma16816(float& c0, float& c1, float& c2, float& c3,
                                         uint32_t a0, uint32_t a1, uint32_t a2, uint32_t a3,
                                         uint32_t b0, uint32_t b1) {
    asm volatile("mma.sync.aligned.m16n8k16.row.col.f32.bf16.bf16.f32 "
                 "{%0,%1,%2,%3}, {%4,%5,%6,%7}, {%8,%9}, {%0,%1,%2,%3};"
                 : "+f"(c0), "+f"(c1), "+f"(c2), "+f"(c3)
                 : "r"(a0), "r"(a1), "r"(a2), "r"(a3), "r"(b0), "r"(b1));
}

// ---------------- kernel 1: G = W^T W (fp32 -> bf16) + W bf16 pair layout ----------------
__global__ void k_G(const float* __restrict__ W) {
    int c1 = blockIdx.x, c2 = threadIdx.x;
    float acc = 0.f;
    #pragma unroll 4
    for (int d = 0; d < D_; d++) acc += W[d * DC + c1] * W[d * DC + c2];
    g_G[c1 * DC + c2] = __float2bfloat16(acc);
    // pair-layout bf16 W: grid*block = 128*128 = exactly (D_/2)*DC entries
    int d2 = c1, c = c2;
    g_Wb2[d2 * DC + c] = __floats2bfloat162_rn(W[(2 * d2) * DC + c], W[(2 * d2 + 1) * DC + c]);
}

// ---------------- kernel 2: q~ = q @ W (tiled, W in smem) + q_sq ----------------
#define QROWS 16
#define SMEM_PREPQ ((D_ / 2) * DC * 4 + QROWS * D_ * 4 + 256)

__global__ void k_prepq(const float* __restrict__ q) {
    extern __shared__ char sm[];
    __nv_bfloat162* Ws2  = (__nv_bfloat162*)sm;               // [128][128] pairs, 64KB
    float*          qs   = (float*)(Ws2 + (D_ / 2) * DC);     // [16][256], 16KB
    float*          qsqs = qs + QROWS * D_;                   // [16]

    const int t  = threadIdx.x;          // 256
    const int r0 = blockIdx.x * QROWS;   // global row

    if (t < QROWS) qsqs[t] = 0.f;
    __syncthreads();

    // load W tile (64KB) as uint4
    {
        const uint4* src = (const uint4*)g_Wb2;
        uint4* dst = (uint4*)Ws2;
        #pragma unroll
        for (int i = 0; i < 16; i++) dst[t + i * 256] = src[t + i * 256];
    }
    // load q rows + partial square sums
    {
        const float4* src = (const float4*)(q + (size_t)r0 * D_);
        #pragma unroll
        for (int i = 0; i < 4; i++) {
            int idx = t + i * 256;             // float4 index, 1024 total
            float4 v = src[idx];
            ((float4*)qs)[idx] = v;
            atomicAdd(&qsqs[idx >> 6], v.x * v.x + v.y * v.y + v.z * v.z + v.w * v.w);
        }
    }
    __syncthreads();

    const int c  = t & 127;
    const int rb = (t >> 7) * 8;
    float acc[8];
    #pragma unroll
    for (int i = 0; i < 8; i++) acc[i] = 0.f;

    #pragma unroll 4
    for (int d2 = 0; d2 < D_ / 2; d2++) {
        float2 w = __bfloat1622float2(Ws2[d2 * DC + c]);
        #pragma unroll
        for (int i = 0; i < 8; i++) {
            float2 qv = *(const float2*)&qs[(rb + i) * D_ + 2 * d2];
            acc[i] = fmaf(qv.x, w.x, acc[i]);
            acc[i] = fmaf(qv.y, w.y, acc[i]);
        }
    }
    #pragma unroll
    for (int i = 0; i < 8; i++)
        g_qt[(size_t)(r0 + rb + i) * DC + c] = __float2bfloat16(acc[i]);
    if (t < QROWS) g_qsq[r0 + t] = qsqs[t];
}

// ---------------- kernel 3: dequant codes + k_sq = kc^T G kc ----------------
#define PSTRIDE 136
#define SMEM_PREPK (2 * 128 * PSTRIDE * 2 + 512)

__global__ void k_prepk(const int* __restrict__ kq,
                        const float* __restrict__ kscale,
                        const float* __restrict__ kzero) {
    extern __shared__ char sm[];
    __nv_bfloat16* kcs  = (__nv_bfloat16*)sm;                 // [128][136]
    __nv_bfloat16* Gs   = kcs + 128 * PSTRIDE;                // [128][136]
    float*         ksqs = (float*)(Gs + 128 * PSTRIDE);       // [128]

    const int t    = threadIdx.x;        // 256
    const int row0 = blockIdx.x * 128;   // global row in [0, B*LK)
    const int b    = row0 / LK;

    {
        const int c4 = (t & 31) * 4;
        const float4 sc = *(const float4*)(kscale + b * DC + c4);
        const float4 zr = *(const float4*)(kzero + b * DC + c4);
        const int rb = t >> 5;
        #pragma unroll
        for (int i = 0; i < 16; i++) {
            const int r = rb + i * 8;
            const int4 code = *(const int4*)(kq + (size_t)(row0 + r) * DC + c4);
            __nv_bfloat162 p0, p1;
            p0.x = __float2bfloat16(sc.x * ((float)code.x - zr.x));
            p0.y = __float2bfloat16(sc.y * ((float)code.y - zr.y));
            p1.x = __float2bfloat16(sc.z * ((float)code.z - zr.z));
            p1.y = __float2bfloat16(sc.w * ((float)code.w - zr.w));
            *(__nv_bfloat162*)&kcs[r * PSTRIDE + c4]     = p0;
            *(__nv_bfloat162*)&kcs[r * PSTRIDE + c4 + 2] = p1;
            *(__nv_bfloat162*)&g_kc[(size_t)(row0 + r) * DC + c4]     = p0;
            *(__nv_bfloat162*)&g_kc[(size_t)(row0 + r) * DC + c4 + 2] = p1;
        }
    }
    {
        const int r = t >> 1, ch = (t & 1) * 64;
        const uint4* src = (const uint4*)(g_G + r * DC + ch);
        #pragma unroll
        for (int i = 0; i < 8; i++) *(uint4*)&Gs[r * PSTRIDE + ch + i * 8] = src[i];
    }
    if (t < 128) ksqs[t] = 0.f;
    __syncthreads();

    const int w = t >> 5, lane = t & 31;
    const int m0 = (w >> 2) * 64, n0 = (w & 3) * 32;
    const int gid = lane >> 2, tid2 = lane & 3;
    const int arow = lane & 15, acol = ((lane >> 4) << 3);
    const int brow = lane & 7,  bcol = (((lane >> 3) & 1) << 3);

    float acc[4][4][4];
    #pragma unroll
    for (int i = 0; i < 4; i++)
        #pragma unroll
        for (int j = 0; j < 4; j++)
            #pragma unroll
            for (int c = 0; c < 4; c++) acc[i][j][c] = 0.f;

    #pragma unroll
    for (int ks = 0; ks < 8; ks++) {
        const int k0 = ks * 16;
        uint32_t A[4][4], Bf[4][2];
        #pragma unroll
        for (int ms = 0; ms < 4; ms++)
            ldsm4(A[ms][0], A[ms][1], A[ms][2], A[ms][3],
                  sptr(&kcs[(m0 + ms * 16 + arow) * PSTRIDE + k0 + acol]));
        #pragma unroll
        for (int ns = 0; ns < 4; ns++)
            ldsm2(Bf[ns][0], Bf[ns][1],
                  sptr(&Gs[(n0 + ns * 8 + brow) * PSTRIDE + k0 + bcol]));
        #pragma unroll
        for (int ms = 0; ms < 4; ms++)
            #pragma unroll
            for (int ns = 0; ns < 4; ns++)
                mma16816(acc[ms][ns][0], acc[ms][ns][1], acc[ms][ns][2], acc[ms][ns][3],
                         A[ms][0], A[ms][1], A[ms][2], A[ms][3], Bf[ns][0], Bf[ns][1]);
    }

    #pragma unroll
    for (int ms = 0; ms < 4; ms++) {
        const int rA = m0 + ms * 16 + gid, rB = rA + 8;
        float sA = 0.f, sB = 0.f;
        #pragma unroll
        for (int ns = 0; ns < 4; ns++) {
            const int c0 = n0 + ns * 8 + tid2 * 2;
            sA += acc[ms][ns][0] * __bfloat162float(kcs[rA * PSTRIDE + c0]);
            sA += acc[ms][ns][1] * __bfloat162float(kcs[rA * PSTRIDE + c0 + 1]);
            sB += acc[ms][ns][2] * __bfloat162float(kcs[rB * PSTRIDE + c0]);
            sB += acc[ms][ns][3] * __bfloat162float(kcs[rB * PSTRIDE + c0 + 1]);
        }
        atomicAdd(&ksqs[rA], sA);
        atomicAdd(&ksqs[rB], sB);
    }
    __syncthreads();
    if (t < 128) g_ksq[row0 + t] = ksqs[t];
}

// ---------------- kernel 4: main — qk MMA + hyperbolic distance ----------------
#define SMEM_MAIN (2 * 128 * PSTRIDE * 2 + 4 * 128 * 4 + 256)

// acosh(1 + t) = log(1 + t + sqrt(t*(t+2))), t >= 0
__device__ __forceinline__ float dist_f(float sq /*qs+ks*/, float rr /*rq*rk*/, float qk) {
    float diff = fmaxf(fmaf(-2.f, qk, sq), 0.f);
    float den  = rr + EPSF;
    float t    = 2.f * diff * fast_rcp(den);
    float s    = fast_sqrt(fmaf(t, t, t + t));
    float arg  = 1.f + t + s;
    return 0.69314718055994531f * fast_lg2(arg);
}

__global__ void k_main(float* __restrict__ out) {
    extern __shared__ char sm[];
    __nv_bfloat16* qts  = (__nv_bfloat16*)sm;             // [128][136]
    __nv_bfloat16* kcs  = qts + 128 * PSTRIDE;            // [128][136]
    float*         qsqs = (float*)(kcs + 128 * PSTRIDE);  // [128]
    float*         rqs  = qsqs + 128;                     // [128]
    float*         ksqs = rqs + 128;                      // [128]
    float*         rks  = ksqs + 128;                     // [128]

    const int t = threadIdx.x;                            // 256
    const int kb = blockIdx.x, qb = blockIdx.y, b = blockIdx.z;
    const int q0 = qb * 128, k0t = kb * 128;

    {
        const int r = t >> 1, ch = (t & 1) * 64;
        const uint4* s1 = (const uint4*)(g_qt + ((size_t)(b * LQ + q0 + r)) * DC + ch);
        const uint4* s2 = (const uint4*)(g_kc + ((size_t)(b * LK + k0t + r)) * DC + ch);
        #pragma unroll
        for (int i = 0; i < 8; i++) *(uint4*)&qts[r * PSTRIDE + ch + i * 8] = s1[i];
        #pragma unroll
        for (int i = 0; i < 8; i++) *(uint4*)&kcs[r * PSTRIDE + ch + i * 8] = s2[i];
    }
    if (t < 128) {
        float qs = g_qsq[b * LQ + q0 + t];
        float ks = g_ksq[b * LK + k0t + t];
        qsqs[t] = qs;
        ksqs[t] = ks;
        rqs[t] = 1.f - fminf(qs, 1.f - EPSF);
        rks[t] = 1.f - fminf(ks, 1.f - EPSF);
    }
    __syncthreads();

    const int w = t >> 5, lane = t & 31;
    const int m0 = (w >> 2) * 64, n0 = (w & 3) * 32;
    const int gid = lane >> 2, tid2 = lane & 3;
    const int arow = lane & 15, acol = ((lane >> 4) << 3);
    const int brow = lane & 7,  bcol = (((lane >> 3) & 1) << 3);

    float acc[4][4][4];
    #pragma unroll
    for (int i = 0; i < 4; i++)
        #pragma unroll
        for (int j = 0; j < 4; j++)
            #pragma unroll
            for (int c = 0; c < 4; c++) acc[i][j][c] = 0.f;

    #pragma unroll
    for (int ks = 0; ks < 8; ks++) {
        const int k0 = ks * 16;
        uint32_t A[4][4], Bf[4][2];
        #pragma unroll
        for (int ms = 0; ms < 4; ms++)
            ldsm4(A[ms][0], A[ms][1], A[ms][2], A[ms][3],
                  sptr(&qts[(m0 + ms * 16 + arow) * PSTRIDE + k0 + acol]));
        #pragma unroll
        for (int ns = 0; ns < 4; ns++)
            ldsm2(Bf[ns][0], Bf[ns][1],
                  sptr(&kcs[(n0 + ns * 8 + brow) * PSTRIDE + k0 + bcol]));
        #pragma unroll
        for (int ms = 0; ms < 4; ms++)
            #pragma unroll
            for (int ns = 0; ns < 4; ns++)
                mma16816(acc[ms][ns][0], acc[ms][ns][1], acc[ms][ns][2], acc[ms][ns][3],
                         A[ms][0], A[ms][1], A[ms][2], A[ms][3], Bf[ns][0], Bf[ns][1]);
    }

    #pragma unroll
    for (int ms = 0; ms < 4; ms++) {
        const int rA = m0 + ms * 16 + gid, rB = rA + 8;
        const float qsA = qsqs[rA], qsB = qsqs[rB];
        const float rqA = rqs[rA],  rqB = rqs[rB];
        const size_t baseA = ((size_t)(b * LQ + q0 + rA)) * LK + k0t;
        const size_t baseB = baseA + (size_t)8 * LK;
        #pragma unroll
        for (int ns = 0; ns < 4; ns++) {
            const int c0 = n0 + ns * 8 + tid2 * 2;
            const float ks0 = ksqs[c0], ks1 = ksqs[c0 + 1];
            const float rk0 = rks[c0],  rk1 = rks[c0 + 1];
            float2 o0, o1;
            o0.x = dist_f(qsA + ks0, rqA * rk0, acc[ms][ns][0]);
            o0.y = dist_f(qsA + ks1, rqA * rk1, acc[ms][ns][1]);
            o1.x = dist_f(qsB + ks0, rqB * rk0, acc[ms][ns][2]);
            o1.y = dist_f(qsB + ks1, rqB * rk1, acc[ms][ns][3]);
            *(float2*)(out + baseA + c0) = o0;
            *(float2*)(out + baseB + c0) = o1;
        }
    }
}

// ---------------- launch ----------------
extern "C" void kernel_launch(void* const* d_in, const int* in_sizes, int n_in,
                              void* d_out, int out_size) {
    const float* q   = (const float*)d_in[0];
    const int*   kq  = (const int*)d_in[1];
    const float* ksc = (const float*)d_in[2];
    const float* kz  = (const float*)d_in[3];
    const float* W   = (const float*)d_in[4];
    float* out = (float*)d_out;
    (void)in_sizes; (void)n_in; (void)out_size;

    cudaFuncSetAttribute(k_prepq, cudaFuncAttributeMaxDynamicSharedMemorySize, SMEM_PREPQ);
    cudaFuncSetAttribute(k_prepk, cudaFuncAttributeMaxDynamicSharedMemorySize, SMEM_PREPK);
    cudaFuncSetAttribute(k_main,  cudaFuncAttributeMaxDynamicSharedMemorySize, SMEM_MAIN);

    k_G<<<DC, DC>>>(W);
    k_prepq<<<(B_ * LQ) / QROWS, 256, SMEM_PREPQ>>>(q);
    k_prepk<<<(B_ * LK) / 128, 256, SMEM_PREPK>>>(kq, ksc, kz);
    k_main<<<dim3(LK / 128, LQ / 128, B_), 256, SMEM_MAIN>>>(out);
}

// round 3
// speedup vs baseline: 1.4480x; 1.1528x over previous
#include <cuda_runtime.h>
#include <cuda_bf16.h>
#include <cstdint>
#include <cmath>

#define B_   8
#define LQ   1024
#define LK   8192
#define D_   256
#define DC   128
#define EPSF 1e-6f
#define LN2F 0.69314718055994531f

// ---------------- scratch (no allocations allowed) ----------------
__device__ __nv_bfloat16  g_qt[B_ * LQ * DC];     // q~ = q @ W_up     (2 MB)
__device__ float          g_qsq[B_ * LQ];
__device__ __nv_bfloat16  g_kc[B_ * LK * DC];     // dequantized codes (16 MB)
__device__ float          g_ksq[B_ * LK];
__device__ __nv_bfloat16  g_G[DC * DC];           // G = W^T W (bf16)
__device__ __nv_bfloat16  g_Wt[DC * D_];          // W^T (c-major): Wt[c][d] = W[d][c]

// ---------------- fast math ----------------
__device__ __forceinline__ float fast_rcp(float x)  { float r; asm("rcp.approx.f32 %0, %1;"  : "=f"(r) : "f"(x)); return r; }
__device__ __forceinline__ float fast_sqrt(float x) { float r; asm("sqrt.approx.f32 %0, %1;" : "=f"(r) : "f"(x)); return r; }
__device__ __forceinline__ float fast_lg2(float x)  { float r; asm("lg2.approx.f32 %0, %1;"  : "=f"(r) : "f"(x)); return r; }

// ---------------- mma helpers ----------------
__device__ __forceinline__ uint32_t sptr(const void* p) {
    return (uint32_t)__cvta_generic_to_shared(p);
}
__device__ __forceinline__ void ldsm4(uint32_t& a0, uint32_t& a1, uint32_t& a2, uint32_t& a3, uint32_t addr) {
    asm volatile("ldmatrix.sync.aligned.m8n8.x4.shared.b16 {%0,%1,%2,%3}, [%4];"
                 : "=r"(a0), "=r"(a1), "=r"(a2), "=r"(a3) : "r"(addr));
}
__device__ __forceinline__ void ldsm2(uint32_t& b0, uint32_t& b1, uint32_t addr) {
    asm volatile("ldmatrix.sync.aligned.m8n8.x2.shared.b16 {%0,%1}, [%2];"
                 : "=r"(b0), "=r"(b1) : "r"(addr));
}
__device__ __forceinline__ void mma16816(float& c0, float& c1, float& c2, float& c3,
                                         uint32_t a0, uint32_t a1, uint32_t a2, uint32_t a3,
                                         uint32_t b0, uint32_t b1) {
    asm volatile("mma.sync.aligned.m16n8k16.row.col.f32.bf16.bf16.f32 "
                 "{%0,%1,%2,%3}, {%4,%5,%6,%7}, {%8,%9}, {%0,%1,%2,%3};"
                 : "+f"(c0), "+f"(c1), "+f"(c2), "+f"(c3)
                 : "r"(a0), "r"(a1), "r"(a2), "r"(a3), "r"(b0), "r"(b1));
}

// ---------------- kernel 1: G = W^T W (bf16) + Wt bf16 ----------------
__global__ void k_G(const float* __restrict__ W) {
    __shared__ float col[D_];
    __shared__ float red[256];
    const int c1 = blockIdx.x;          // 128 blocks
    const int t  = threadIdx.x;         // 256 threads
    const int c2 = t & 127, h = t >> 7;

    float wv = W[t * DC + c1];          // column c1 of W (t = d)
    col[t] = wv;
    g_Wt[c1 * D_ + t] = __float2bfloat16(wv);
    __syncthreads();

    float acc = 0.f;
    const int d0 = h * 128;
    #pragma unroll 8
    for (int d = 0; d < 128; d++) acc += col[d0 + d] * W[(d0 + d) * DC + c2];
    red[t] = acc;
    __syncthreads();
    if (h == 0) g_G[c1 * DC + c2] = __float2bfloat16(red[c2] + red[c2 + 128]);
}

// ---------------- kernel 2: q~ = q @ W via MMA + q_sq ----------------
#define QSTRIDE 264
#define SMEM_PREPQ (128 * QSTRIDE * 2 * 2 + 256 * 4 + 128 * 4 + 256)

__global__ void k_prepq(const float* __restrict__ q) {
    extern __shared__ char sm[];
    __nv_bfloat16* qs  = (__nv_bfloat16*)sm;               // [128][264] bf16
    __nv_bfloat16* Wts = qs + 128 * QSTRIDE;               // [128][264] bf16
    float*         par = (float*)(Wts + 128 * QSTRIDE);    // [256]
    float*         qsq = par + 256;                        // [128]

    const int t  = threadIdx.x;          // 256
    const int r0 = blockIdx.x * 128;     // 64 blocks

    // load q tile -> bf16 smem
    {
        const float4* src = (const float4*)(q + (size_t)r0 * D_);
        #pragma unroll
        for (int i = 0; i < 32; i++) {
            int idx = t + i * 256;                 // 8192 float4
            int row = idx >> 6, c4 = (idx & 63) * 4;
            float4 v = src[idx];
            *(__nv_bfloat162*)&qs[row * QSTRIDE + c4]     = __floats2bfloat162_rn(v.x, v.y);
            *(__nv_bfloat162*)&qs[row * QSTRIDE + c4 + 2] = __floats2bfloat162_rn(v.z, v.w);
        }
    }
    // qsq in fp32 from global (L2 hot): 2 threads per row
    {
        const float4* rowp = (const float4*)(q + (size_t)(r0 + (t >> 1)) * D_) + (t & 1) * 32;
        float ss = 0.f;
        #pragma unroll 8
        for (int i = 0; i < 32; i++) {
            float4 v = rowp[i];
            ss += v.x * v.x + v.y * v.y + v.z * v.z + v.w * v.w;
        }
        par[t] = ss;
    }
    // load W^T tile (64KB)
    {
        #pragma unroll
        for (int i = 0; i < 16; i++) {
            int idx = t + i * 256;                 // 4096 uint4
            int r = idx >> 5, c8 = (idx & 31) * 8;
            *(uint4*)&Wts[r * QSTRIDE + c8] = ((const uint4*)g_Wt)[idx];
        }
    }
    __syncthreads();
    if (t < 128) qsq[t] = par[2 * t] + par[2 * t + 1];

    const int w = t >> 5, lane = t & 31;
    const int m0 = (w >> 2) * 64, n0 = (w & 3) * 32;
    const int gid = lane >> 2, tid2 = lane & 3;
    const int arow = lane & 15, acol = ((lane >> 4) << 3);
    const int brow = lane & 7,  bcol = (((lane >> 3) & 1) << 3);

    float acc[4][4][4];
    #pragma unroll
    for (int i = 0; i < 4; i++)
        #pragma unroll
        for (int j = 0; j < 4; j++)
            #pragma unroll
            for (int c = 0; c < 4; c++) acc[i][j][c] = 0.f;

    #pragma unroll
    for (int ks = 0; ks < 16; ks++) {
        const int k0 = ks * 16;
        uint32_t A[4][4], Bf[4][2];
        #pragma unroll
        for (int ms = 0; ms < 4; ms++)
            ldsm4(A[ms][0], A[ms][1], A[ms][2], A[ms][3],
                  sptr(&qs[(m0 + ms * 16 + arow) * QSTRIDE + k0 + acol]));
        #pragma unroll
        for (int ns = 0; ns < 4; ns++)
            ldsm2(Bf[ns][0], Bf[ns][1],
                  sptr(&Wts[(n0 + ns * 8 + brow) * QSTRIDE + k0 + bcol]));
        #pragma unroll
        for (int ms = 0; ms < 4; ms++)
            #pragma unroll
            for (int ns = 0; ns < 4; ns++)
                mma16816(acc[ms][ns][0], acc[ms][ns][1], acc[ms][ns][2], acc[ms][ns][3],
                         A[ms][0], A[ms][1], A[ms][2], A[ms][3], Bf[ns][0], Bf[ns][1]);
    }

    #pragma unroll
    for (int ms = 0; ms < 4; ms++) {
        const int rA = m0 + ms * 16 + gid, rB = rA + 8;
        #pragma unroll
        for (int ns = 0; ns < 4; ns++) {
            const int c0 = n0 + ns * 8 + tid2 * 2;
            *(__nv_bfloat162*)&g_qt[(size_t)(r0 + rA) * DC + c0] =
                __floats2bfloat162_rn(acc[ms][ns][0], acc[ms][ns][1]);
            *(__nv_bfloat162*)&g_qt[(size_t)(r0 + rB) * DC + c0] =
                __floats2bfloat162_rn(acc[ms][ns][2], acc[ms][ns][3]);
        }
    }
    __syncthreads();
    if (t < 128) g_qsq[r0 + t] = qsq[t];
}

// ---------------- kernel 3: dequant codes + k_sq = kc^T G kc ----------------
#define PSTRIDE 136
#define SMEM_PREPK (2 * 128 * PSTRIDE * 2 + 512)

__global__ void k_prepk(const int* __restrict__ kq,
                        const float* __restrict__ kscale,
                        const float* __restrict__ kzero) {
    extern __shared__ char sm[];
    __nv_bfloat16* kcs  = (__nv_bfloat16*)sm;                 // [128][136]
    __nv_bfloat16* Gs   = kcs + 128 * PSTRIDE;                // [128][136]
    float*         ksqs = (float*)(Gs + 128 * PSTRIDE);       // [128]

    const int t    = threadIdx.x;        // 256
    const int row0 = blockIdx.x * 128;
    const int b    = row0 / LK;

    {
        const int c4 = (t & 31) * 4;
        const float4 sc = *(const float4*)(kscale + b * DC + c4);
        const float4 zr = *(const float4*)(kzero + b * DC + c4);
        const int rb = t >> 5;
        #pragma unroll
        for (int i = 0; i < 16; i++) {
            const int r = rb + i * 8;
            const int4 code = *(const int4*)(kq + (size_t)(row0 + r) * DC + c4);
            __nv_bfloat162 p0, p1;
            p0.x = __float2bfloat16(sc.x * ((float)code.x - zr.x));
            p0.y = __float2bfloat16(sc.y * ((float)code.y - zr.y));
            p1.x = __float2bfloat16(sc.z * ((float)code.z - zr.z));
            p1.y = __float2bfloat16(sc.w * ((float)code.w - zr.w));
            *(__nv_bfloat162*)&kcs[r * PSTRIDE + c4]     = p0;
            *(__nv_bfloat162*)&kcs[r * PSTRIDE + c4 + 2] = p1;
            *(__nv_bfloat162*)&g_kc[(size_t)(row0 + r) * DC + c4]     = p0;
            *(__nv_bfloat162*)&g_kc[(size_t)(row0 + r) * DC + c4 + 2] = p1;
        }
    }
    {
        const int r = t >> 1, ch = (t & 1) * 64;
        const uint4* src = (const uint4*)(g_G + r * DC + ch);
        #pragma unroll
        for (int i = 0; i < 8; i++) *(uint4*)&Gs[r * PSTRIDE + ch + i * 8] = src[i];
    }
    if (t < 128) ksqs[t] = 0.f;
    __syncthreads();

    const int w = t >> 5, lane = t & 31;
    const int m0 = (w >> 2) * 64, n0 = (w & 3) * 32;
    const int gid = lane >> 2, tid2 = lane & 3;
    const int arow = lane & 15, acol = ((lane >> 4) << 3);
    const int brow = lane & 7,  bcol = (((lane >> 3) & 1) << 3);

    float acc[4][4][4];
    #pragma unroll
    for (int i = 0; i < 4; i++)
        #pragma unroll
        for (int j = 0; j < 4; j++)
            #pragma unroll
            for (int c = 0; c < 4; c++) acc[i][j][c] = 0.f;

    #pragma unroll
    for (int ks = 0; ks < 8; ks++) {
        const int k0 = ks * 16;
        uint32_t A[4][4], Bf[4][2];
        #pragma unroll
        for (int ms = 0; ms < 4; ms++)
            ldsm4(A[ms][0], A[ms][1], A[ms][2], A[ms][3],
                  sptr(&kcs[(m0 + ms * 16 + arow) * PSTRIDE + k0 + acol]));
        #pragma unroll
        for (int ns = 0; ns < 4; ns++)
            ldsm2(Bf[ns][0], Bf[ns][1],
                  sptr(&Gs[(n0 + ns * 8 + brow) * PSTRIDE + k0 + bcol]));
        #pragma unroll
        for (int ms = 0; ms < 4; ms++)
            #pragma unroll
            for (int ns = 0; ns < 4; ns++)
                mma16816(acc[ms][ns][0], acc[ms][ns][1], acc[ms][ns][2], acc[ms][ns][3],
                         A[ms][0], A[ms][1], A[ms][2], A[ms][3], Bf[ns][0], Bf[ns][1]);
    }

    #pragma unroll
    for (int ms = 0; ms < 4; ms++) {
        const int rA = m0 + ms * 16 + gid, rB = rA + 8;
        float sA = 0.f, sB = 0.f;
        #pragma unroll
        for (int ns = 0; ns < 4; ns++) {
            const int c0 = n0 + ns * 8 + tid2 * 2;
            sA += acc[ms][ns][0] * __bfloat162float(kcs[rA * PSTRIDE + c0]);
            sA += acc[ms][ns][1] * __bfloat162float(kcs[rA * PSTRIDE + c0 + 1]);
            sB += acc[ms][ns][2] * __bfloat162float(kcs[rB * PSTRIDE + c0]);
            sB += acc[ms][ns][3] * __bfloat162float(kcs[rB * PSTRIDE + c0 + 1]);
        }
        atomicAdd(&ksqs[rA], sA);
        atomicAdd(&ksqs[rB], sB);
    }
    __syncthreads();
    if (t < 128) g_ksq[row0 + t] = ksqs[t];
}

// ---------------- kernel 4: main — qk MMA + hyperbolic distance ----------------
#define OSTRIDE 132
#define SMEM_MAIN (2 * 128 * PSTRIDE * 2 + 4 * 128 * 4 + 256)

__global__ void k_main(float* __restrict__ out) {
    extern __shared__ char sm[];
    __nv_bfloat16* qts  = (__nv_bfloat16*)sm;             // [128][136] (mainloop)
    __nv_bfloat16* kcs  = qts + 128 * PSTRIDE;            // [128][136]
    float*         stg  = (float*)sm;                     // [128][132] (epilogue, reuses tiles)
    float*         qsqs = (float*)(kcs + 128 * PSTRIDE);  // [128]
    float*         rqs  = qsqs + 128;
    float*         ksqs = rqs + 128;
    float*         rks  = ksqs + 128;

    const int t = threadIdx.x;                            // 256
    const int kb = blockIdx.x, qb = blockIdx.y, b = blockIdx.z;
    const int q0 = qb * 128, k0t = kb * 128;

    {
        const int r = t >> 1, ch = (t & 1) * 64;
        const uint4* s1 = (const uint4*)(g_qt + ((size_t)(b * LQ + q0 + r)) * DC + ch);
        const uint4* s2 = (const uint4*)(g_kc + ((size_t)(b * LK + k0t + r)) * DC + ch);
        #pragma unroll
        for (int i = 0; i < 8; i++) *(uint4*)&qts[r * PSTRIDE + ch + i * 8] = s1[i];
        #pragma unroll
        for (int i = 0; i < 8; i++) *(uint4*)&kcs[r * PSTRIDE + ch + i * 8] = s2[i];
    }
    if (t < 128) {
        float qs = g_qsq[b * LQ + q0 + t];
        float ks = g_ksq[b * LK + k0t + t];
        qsqs[t] = qs;
        ksqs[t] = ks;
        rqs[t] = 1.f - fminf(qs, 1.f - EPSF);
        rks[t] = 1.f - fminf(ks, 1.f - EPSF);
    }
    __syncthreads();

    const int w = t >> 5, lane = t & 31;
    const int m0 = (w >> 2) * 64, n0 = (w & 3) * 32;
    const int gid = lane >> 2, tid2 = lane & 3;
    const int arow = lane & 15, acol = ((lane >> 4) << 3);
    const int brow = lane & 7,  bcol = (((lane >> 3) & 1) << 3);

    float acc[4][4][4];
    #pragma unroll
    for (int i = 0; i < 4; i++)
        #pragma unroll
        for (int j = 0; j < 4; j++)
            #pragma unroll
            for (int c = 0; c < 4; c++) acc[i][j][c] = 0.f;

    #pragma unroll
    for (int ks = 0; ks < 8; ks++) {
        const int k0 = ks * 16;
        uint32_t A[4][4], Bf[4][2];
        #pragma unroll
        for (int ms = 0; ms < 4; ms++)
            ldsm4(A[ms][0], A[ms][1], A[ms][2], A[ms][3],
                  sptr(&qts[(m0 + ms * 16 + arow) * PSTRIDE + k0 + acol]));
        #pragma unroll
        for (int ns = 0; ns < 4; ns++)
            ldsm2(Bf[ns][0], Bf[ns][1],
                  sptr(&kcs[(n0 + ns * 8 + brow) * PSTRIDE + k0 + bcol]));
        #pragma unroll
        for (int ms = 0; ms < 4; ms++)
            #pragma unroll
            for (int ns = 0; ns < 4; ns++)
                mma16816(acc[ms][ns][0], acc[ms][ns][1], acc[ms][ns][2], acc[ms][ns][3],
                         A[ms][0], A[ms][1], A[ms][2], A[ms][3], Bf[ns][0], Bf[ns][1]);
    }

    __syncthreads();   // tiles dead; reuse as staging

    // distance epilogue into smem staging
    #pragma unroll
    for (int ms = 0; ms < 4; ms++) {
        const int rA = m0 + ms * 16 + gid, rB = rA + 8;
        const float qsA = qsqs[rA], qsB = qsqs[rB];
        const float rqA = rqs[rA],  rqB = rqs[rB];
        #pragma unroll
        for (int ns = 0; ns < 4; ns++) {
            const int c0 = n0 + ns * 8 + tid2 * 2;
            const float ks0 = ksqs[c0], ks1 = ksqs[c0 + 1];
            const float rk0 = rks[c0],  rk1 = rks[c0 + 1];

            float u[4], dn[4], dist[4];
            u[0] = 2.f * fmaxf(fmaf(-2.f, acc[ms][ns][0], qsA + ks0), 0.f); dn[0] = fmaf(rqA, rk0, EPSF);
            u[1] = 2.f * fmaxf(fmaf(-2.f, acc[ms][ns][1], qsA + ks1), 0.f); dn[1] = fmaf(rqA, rk1, EPSF);
            u[2] = 2.f * fmaxf(fmaf(-2.f, acc[ms][ns][2], qsB + ks0), 0.f); dn[2] = fmaf(rqB, rk0, EPSF);
            u[3] = 2.f * fmaxf(fmaf(-2.f, acc[ms][ns][3], qsB + ks1), 0.f); dn[3] = fmaf(rqB, rk1, EPSF);

            bool bad = false;
            #pragma unroll
            for (int j = 0; j < 4; j++) {
                // acosh(1+t), t = u/dn, t >> 1:  ln2*(1 + lg2(u+dn) - lg2(dn))
                dist[j] = LN2F * (1.f + fast_lg2(u[j] + dn[j]) - fast_lg2(dn[j]));
                bad |= (u[j] < 100.f * dn[j]);
            }
            if (bad) {       // exact path (never taken for this data distribution)
                #pragma unroll
                for (int j = 0; j < 4; j++) {
                    float tt = u[j] * fast_rcp(dn[j]);
                    float s  = fast_sqrt(fmaf(tt, tt, 2.f * tt));
                    dist[j] = LN2F * fast_lg2(1.f + tt + s);
                }
            }
            *(float2*)&stg[rA * OSTRIDE + c0] = make_float2(dist[0], dist[1]);
            *(float2*)&stg[rB * OSTRIDE + c0] = make_float2(dist[2], dist[3]);
        }
    }
    __syncthreads();

    // coalesced streaming stores: warp w handles rows w*16..w*16+15
    {
        const size_t obase = ((size_t)(b * LQ + q0)) * LK + k0t;
        #pragma unroll
        for (int it = 0; it < 16; it++) {
            const int r = w * 16 + it;
            float4 v = *(float4*)&stg[r * OSTRIDE + lane * 4];
            __stcs((float4*)(out + obase + (size_t)r * LK) + lane, v);
        }
    }
}

// ---------------- launch ----------------
extern "C" void kernel_launch(void* const* d_in, const int* in_sizes, int n_in,
                              void* d_out, int out_size) {
    const float* q   = (const float*)d_in[0];
    const int*   kq  = (const int*)d_in[1];
    const float* ksc = (const float*)d_in[2];
    const float* kz  = (const float*)d_in[3];
    const float* W   = (const float*)d_in[4];
    float* out = (float*)d_out;
    (void)in_sizes; (void)n_in; (void)out_size;

    cudaFuncSetAttribute(k_prepq, cudaFuncAttributeMaxDynamicSharedMemorySize, SMEM_PREPQ);
    cudaFuncSetAttribute(k_prepk, cudaFuncAttributeMaxDynamicSharedMemorySize, SMEM_PREPK);
    cudaFuncSetAttribute(k_main,  cudaFuncAttributeMaxDynamicSharedMemorySize, SMEM_MAIN);

    k_G<<<DC, 256>>>(W);
    k_prepq<<<(B_ * LQ) / 128, 256, SMEM_PREPQ>>>(q);
    k_prepk<<<(B_ * LK) / 128, 256, SMEM_PREPK>>>(kq, ksc, kz);
    k_main<<<dim3(LK / 128, LQ / 128, B_), 256, SMEM_MAIN>>>(out);
}